// round 5
// baseline (speedup 1.0000x reference)
#include <cuda_runtime.h>
#include <cuda_fp16.h>
#include <cstdint>
#include <cstddef>

// ---------------------------------------------------------------------------
// Problem constants
// ---------------------------------------------------------------------------
#define OUT_F 4096
#define IN_F  4096
#define M_TOTAL 8192           // 4 * 2048

// GEMM tiling (fp16 mma.sync path — generic PTX, safe under target sm_100)
#define BM 128
#define BN 128
#define BK 64                  // halfs per k-slice = 128 bytes per row (SW128)
#define STAGES 5
#define K_ITERS (IN_F / BK)    // 64
#define A_STAGE_BYTES (BM * BK * 2)            // 16384
#define B_STAGE_BYTES (BN * BK * 2)            // 16384
#define STAGE_BYTES (A_STAGE_BYTES + B_STAGE_BYTES)  // 32768
#define SMEM_TOTAL (STAGES * STAGE_BYTES)      // 163840

// ---------------------------------------------------------------------------
// Scratch (allocation-free rule: __device__ globals)
// ---------------------------------------------------------------------------
__device__ __align__(256) __half g_xh[(size_t)M_TOTAL * IN_F];  // x in fp16
__device__ __align__(256) __half g_wh[(size_t)OUT_F * IN_F];    // dequantized W in fp16

// ---------------------------------------------------------------------------
// Helpers
// ---------------------------------------------------------------------------
__device__ __forceinline__ uint32_t smem_u32(const void* p) {
    uint32_t a;
    asm("{ .reg .u64 t; cvta.to.shared.u64 t, %1; cvt.u32.u64 %0, t; }" : "=r"(a) : "l"(p));
    return a;
}

__device__ __forceinline__ uint32_t h2_bits(__half2 h) {
    return *reinterpret_cast<uint32_t*>(&h);
}

#define SWZ(off) ((off) ^ (((off) >> 3) & 0x70))

#define CP_ASYNC16(saddr, gptr) \
    asm volatile("cp.async.cg.shared.global [%0], [%1], 16;" :: "r"(saddr), "l"(gptr))
#define CP_ASYNC_COMMIT() asm volatile("cp.async.commit_group;" ::: "memory")
#define CP_ASYNC_WAIT(n)  asm volatile("cp.async.wait_group %0;" :: "n"(n) : "memory")

#define LDMATRIX_X4(r0, r1, r2, r3, addr)                                     \
    asm volatile("ldmatrix.sync.aligned.m8n8.x4.shared.b16 {%0,%1,%2,%3}, [%4];" \
                 : "=r"(r0), "=r"(r1), "=r"(r2), "=r"(r3) : "r"(addr))

#define MMA_16816(c, a0, a1, a2, a3, b0, b1)                                  \
    asm volatile("mma.sync.aligned.m16n8k16.row.col.f32.f16.f16.f32 "         \
                 "{%0,%1,%2,%3}, {%4,%5,%6,%7}, {%8,%9}, {%0,%1,%2,%3};"      \
                 : "+f"((c)[0]), "+f"((c)[1]), "+f"((c)[2]), "+f"((c)[3])     \
                 : "r"(a0), "r"(a1), "r"(a2), "r"(a3), "r"(b0), "r"(b1))

// Streaming store: C is write-once, never re-read -> don't pollute L2
// (protects the B panel other CTAs in the supertile group are reusing).
__device__ __forceinline__ void stcs_f2(float* p, float a, float b) {
    asm volatile("st.global.cs.v2.f32 [%0], {%1, %2};" :: "l"(p), "f"(a), "f"(b) : "memory");
}

// ---------------------------------------------------------------------------
// Prep kernel 1: x (fp32) -> fp16
// ---------------------------------------------------------------------------
__global__ void __launch_bounds__(256) conv_x_kernel(const float* __restrict__ x) {
    size_t j = (size_t)blockIdx.x * blockDim.x + threadIdx.x;   // [0, 8388608)
    float4 v = reinterpret_cast<const float4*>(x)[j];
    uint2 o;
    o.x = h2_bits(__floats2half2_rn(v.x, v.y));
    o.y = h2_bits(__floats2half2_rn(v.z, v.w));
    reinterpret_cast<uint2*>(g_xh)[j] = o;
}

// ---------------------------------------------------------------------------
// Prep kernel 2: HQQ int4 dequant -> fp16
// Each packed value is one byte stored as int32. Thread handles 4 packed
// bytes (int4 load) -> 8 weights -> 16B store. Group = 8j/64 = j/8.
// ---------------------------------------------------------------------------
__global__ void __launch_bounds__(256) dequant_w_kernel(
    const int* __restrict__ Wq, const float* __restrict__ scale,
    const float* __restrict__ zero) {
    size_t j = (size_t)blockIdx.x * blockDim.x + threadIdx.x;   // [0, 2097152)
    int4 v = reinterpret_cast<const int4*>(Wq)[j];
    size_t g = j >> 3;
    float s = scale[g];
    float z = zero[g];
    uint4 o;
    o.x = h2_bits(__floats2half2_rn(((float)(v.x & 15) - z) * s,
                                    ((float)(v.x >> 4) - z) * s));
    o.y = h2_bits(__floats2half2_rn(((float)(v.y & 15) - z) * s,
                                    ((float)(v.y >> 4) - z) * s));
    o.z = h2_bits(__floats2half2_rn(((float)(v.z & 15) - z) * s,
                                    ((float)(v.z >> 4) - z) * s));
    o.w = h2_bits(__floats2half2_rn(((float)(v.w & 15) - z) * s,
                                    ((float)(v.w >> 4) - z) * s));
    reinterpret_cast<uint4*>(g_wh)[j] = o;
}

// ---------------------------------------------------------------------------
// GEMM: C[M_TOTAL, OUT_F] = g_xh @ g_wh^T (fp16 in, fp32 accum)
// 256 threads = 8 warps as 2(m) x 4(n); warp tile 64x32.
// 5-stage cp.async pipeline, SW128-swizzled smem, ldmatrix fragments.
// ---------------------------------------------------------------------------
__global__ void __launch_bounds__(256, 1) hqq_gemm_f16(float* __restrict__ C) {
    extern __shared__ __align__(1024) char smem[];
    const uint32_t sb = smem_u32(smem);

    const int tid = threadIdx.x;
    const int wid = tid >> 5;
    const int lid = tid & 31;
    const int warp_m = wid >> 2;       // 0..1
    const int warp_n = wid & 3;        // 0..3

    // Supertile mapping: groups of 16 m-tiles across all 32 n-tiles.
    // Wave of ~148 CTAs touches A 16MB + B ~10MB -> L2 resident.
    const int NT = OUT_F / BN;         // 32
    const int GM = 16;
    int bid = blockIdx.x;
    int group = bid / (GM * NT);
    int rem = bid - group * (GM * NT);
    int m_tile = group * GM + (rem % GM);
    int n_tile = rem / GM;

    const __half* Ab = g_xh + (size_t)m_tile * BM * IN_F;
    const __half* Bb = g_wh + (size_t)n_tile * BN * IN_F;

    // ---- stage loader: 2048 x 16B chunks, 8 per thread ----
    auto load_stage = [&](int stage, int kk) {
        uint32_t sA = sb + stage * STAGE_BYTES;
        uint32_t sB = sA + A_STAGE_BYTES;
        const __half* gA = Ab + kk;
        const __half* gB = Bb + kk;
        #pragma unroll
        for (int i = 0; i < 4; i++) {
            int c = tid + i * 256;                 // 0..1023
            int row = c >> 3, c16 = c & 7;
            CP_ASYNC16(sA + SWZ(row * 128 + c16 * 16),
                       gA + (size_t)row * IN_F + c16 * 8);
        }
        #pragma unroll
        for (int i = 0; i < 4; i++) {
            int c = tid + i * 256;
            int row = c >> 3, c16 = c & 7;
            CP_ASYNC16(sB + SWZ(row * 128 + c16 * 16),
                       gB + (size_t)row * IN_F + c16 * 8);
        }
    };

    // Prologue
    #pragma unroll
    for (int s = 0; s < STAGES - 1; s++) {
        load_stage(s, s * BK);
        CP_ASYNC_COMMIT();
    }

    // Accumulators: 4 m-subtiles x 4 n-subtiles x 4 floats
    float acc[4][4][4];
    #pragma unroll
    for (int i = 0; i < 4; i++)
        #pragma unroll
        for (int j = 0; j < 4; j++)
            #pragma unroll
            for (int q = 0; q < 4; q++) acc[i][j][q] = 0.0f;

    // Per-thread ldmatrix address components
    const int a_row = warp_m * 64 + (lid & 15);      // + mt*16
    const int a_kc  = (lid >> 4) * 8;                // k sub-offset
    const int b_row = warp_n * 32 + ((lid >> 4) ? 8 : 0) + (lid & 7);  // + p*16
    const int b_kc  = ((lid >> 3) & 1) * 8;

    for (int k = 0; k < K_ITERS; k++) {
        CP_ASYNC_WAIT(STAGES - 2);   // stage k landed
        __syncthreads();             // all warps past iter k-1 compute

        int kn = k + STAGES - 1;
        if (kn < K_ITERS) load_stage(kn % STAGES, kn * BK);
        CP_ASYNC_COMMIT();           // always commit to keep group count fixed

        const int s = k % STAGES;
        const uint32_t sA = sb + s * STAGE_BYTES;
        const uint32_t sB = sA + A_STAGE_BYTES;

        #pragma unroll
        for (int kk = 0; kk < BK / 16; kk++) {       // 4 k-steps of 16
            uint32_t a[4][4];
            #pragma unroll
            for (int mt = 0; mt < 4; mt++) {
                uint32_t off = (uint32_t)(a_row + mt * 16) * 128
                             + (uint32_t)(kk * 16 + a_kc) * 2;
                LDMATRIX_X4(a[mt][0], a[mt][1], a[mt][2], a[mt][3], sA + SWZ(off));
            }
            uint32_t b[2][4];                        // p covers n-subtiles {2p, 2p+1}
            #pragma unroll
            for (int p = 0; p < 2; p++) {
                uint32_t off = (uint32_t)(b_row + p * 16) * 128
                             + (uint32_t)(kk * 16 + b_kc) * 2;
                LDMATRIX_X4(b[p][0], b[p][1], b[p][2], b[p][3], sB + SWZ(off));
            }
            #pragma unroll
            for (int mt = 0; mt < 4; mt++)
                #pragma unroll
                for (int nt = 0; nt < 4; nt++)
                    MMA_16816(acc[mt][nt],
                              a[mt][0], a[mt][1], a[mt][2], a[mt][3],
                              b[nt >> 1][(nt & 1) * 2], b[nt >> 1][(nt & 1) * 2 + 1]);
        }
    }

    // Epilogue: fragment layout -> global fp32, streaming stores
    const int m0 = m_tile * BM + warp_m * 64 + (lid >> 2);
    const int n0 = n_tile * BN + warp_n * 32 + (lid & 3) * 2;
    #pragma unroll
    for (int mt = 0; mt < 4; mt++) {
        #pragma unroll
        for (int nt = 0; nt < 4; nt++) {
            float* p0 = C + (size_t)(m0 + mt * 16) * OUT_F + (n0 + nt * 8);
            float* p1 = p0 + 8 * OUT_F;
            stcs_f2(p0, acc[mt][nt][0], acc[mt][nt][1]);
            stcs_f2(p1, acc[mt][nt][2], acc[mt][nt][3]);
        }
    }
}

// ---------------------------------------------------------------------------
// Launch
// ---------------------------------------------------------------------------
extern "C" void kernel_launch(void* const* d_in, const int* in_sizes, int n_in,
                              void* d_out, int out_size) {
    const float* x     = (const float*)d_in[0];
    const int*   Wq    = (const int*)d_in[1];
    const float* scale = (const float*)d_in[2];
    const float* zero  = (const float*)d_in[3];
    float* out = (float*)d_out;

    cudaFuncSetAttribute(hqq_gemm_f16, cudaFuncAttributeMaxDynamicSharedMemorySize, SMEM_TOTAL);

    // x: 33,554,432 floats = 8,388,608 float4 chunks
    conv_x_kernel<<<8388608 / 256, 256>>>(x);
    // W_q: 8,388,608 packed bytes = 2,097,152 int4 chunks
    dequant_w_kernel<<<2097152 / 256, 256>>>(Wq, scale, zero);

    int grid = (M_TOTAL / BM) * (OUT_F / BN);   // 2048
    hqq_gemm_f16<<<grid, 256, SMEM_TOTAL>>>(out);
}

// round 6
// speedup vs baseline: 1.1482x; 1.1482x over previous
#include <cuda_runtime.h>
#include <cuda_fp16.h>
#include <cstdint>
#include <cstddef>

// ---------------------------------------------------------------------------
// Problem constants
// ---------------------------------------------------------------------------
#define OUT_F 4096
#define IN_F  4096
#define M_TOTAL 8192           // 4 * 2048

// GEMM tiling (fp16 mma.sync path — generic PTX, safe under target sm_100)
#define BM 128
#define BN 128
#define BK 64                  // halfs per k-slice = 128 bytes per row (SW128)
#define STAGES 5
#define K_ITERS (IN_F / BK)    // 64
#define A_STAGE_BYTES (BM * BK * 2)            // 16384
#define B_STAGE_BYTES (BN * BK * 2)            // 16384
#define STAGE_BYTES (A_STAGE_BYTES + B_STAGE_BYTES)  // 32768
#define SMEM_TOTAL (STAGES * STAGE_BYTES)      // 163840

// ---------------------------------------------------------------------------
// Scratch (allocation-free rule: __device__ globals)
// ---------------------------------------------------------------------------
__device__ __align__(256) __half g_xh[(size_t)M_TOTAL * IN_F];  // x in fp16
__device__ __align__(256) __half g_wh[(size_t)OUT_F * IN_F];    // dequantized W in fp16

// ---------------------------------------------------------------------------
// Helpers
// ---------------------------------------------------------------------------
__device__ __forceinline__ uint32_t smem_u32(const void* p) {
    uint32_t a;
    asm("{ .reg .u64 t; cvta.to.shared.u64 t, %1; cvt.u32.u64 %0, t; }" : "=r"(a) : "l"(p));
    return a;
}

__device__ __forceinline__ uint32_t h2_bits(__half2 h) {
    return *reinterpret_cast<uint32_t*>(&h);
}

#define SWZ(off) ((off) ^ (((off) >> 3) & 0x70))

#define CP_ASYNC16(saddr, gptr) \
    asm volatile("cp.async.cg.shared.global [%0], [%1], 16;" :: "r"(saddr), "l"(gptr))
#define CP_ASYNC_COMMIT() asm volatile("cp.async.commit_group;" ::: "memory")
#define CP_ASYNC_WAIT(n)  asm volatile("cp.async.wait_group %0;" :: "n"(n) : "memory")

#define LDMATRIX_X4(r0, r1, r2, r3, addr)                                     \
    asm volatile("ldmatrix.sync.aligned.m8n8.x4.shared.b16 {%0,%1,%2,%3}, [%4];" \
                 : "=r"(r0), "=r"(r1), "=r"(r2), "=r"(r3) : "r"(addr))

#define MMA_16816(c, a0, a1, a2, a3, b0, b1)                                  \
    asm volatile("mma.sync.aligned.m16n8k16.row.col.f32.f16.f16.f32 "         \
                 "{%0,%1,%2,%3}, {%4,%5,%6,%7}, {%8,%9}, {%0,%1,%2,%3};"      \
                 : "+f"((c)[0]), "+f"((c)[1]), "+f"((c)[2]), "+f"((c)[3])     \
                 : "r"(a0), "r"(a1), "r"(a2), "r"(a3), "r"(b0), "r"(b1))

// Streaming store: C is write-once, never re-read -> don't pollute L2
// (protects the B panel other CTAs in the supertile group are reusing).
__device__ __forceinline__ void stcs_f2(float* p, float a, float b) {
    asm volatile("st.global.cs.v2.f32 [%0], {%1, %2};" :: "l"(p), "f"(a), "f"(b) : "memory");
}

// ---------------------------------------------------------------------------
// Prep kernel 1: x (fp32) -> fp16
// ---------------------------------------------------------------------------
__global__ void __launch_bounds__(256) conv_x_kernel(const float* __restrict__ x) {
    size_t j = (size_t)blockIdx.x * blockDim.x + threadIdx.x;   // [0, 8388608)
    float4 v = reinterpret_cast<const float4*>(x)[j];
    uint2 o;
    o.x = h2_bits(__floats2half2_rn(v.x, v.y));
    o.y = h2_bits(__floats2half2_rn(v.z, v.w));
    reinterpret_cast<uint2*>(g_xh)[j] = o;
}

// ---------------------------------------------------------------------------
// Prep kernel 2: HQQ int4 dequant -> fp16
// ---------------------------------------------------------------------------
__global__ void __launch_bounds__(256) dequant_w_kernel(
    const int* __restrict__ Wq, const float* __restrict__ scale,
    const float* __restrict__ zero) {
    size_t j = (size_t)blockIdx.x * blockDim.x + threadIdx.x;   // [0, 2097152)
    int4 v = reinterpret_cast<const int4*>(Wq)[j];
    size_t g = j >> 3;
    float s = scale[g];
    float z = zero[g];
    uint4 o;
    o.x = h2_bits(__floats2half2_rn(((float)(v.x & 15) - z) * s,
                                    ((float)(v.x >> 4) - z) * s));
    o.y = h2_bits(__floats2half2_rn(((float)(v.y & 15) - z) * s,
                                    ((float)(v.y >> 4) - z) * s));
    o.z = h2_bits(__floats2half2_rn(((float)(v.z & 15) - z) * s,
                                    ((float)(v.z >> 4) - z) * s));
    o.w = h2_bits(__floats2half2_rn(((float)(v.w & 15) - z) * s,
                                    ((float)(v.w >> 4) - z) * s));
    reinterpret_cast<uint4*>(g_wh)[j] = o;
}

// ---------------------------------------------------------------------------
// GEMM: C[M_TOTAL, OUT_F] = g_xh @ g_wh^T (fp16 in, fp32 accum)
// 256 threads = 8 warps as 2(m) x 4(n); warp tile 64x32.
// 5-stage cp.async pipeline + fragment double-buffering.
// ---------------------------------------------------------------------------
__global__ void __launch_bounds__(256, 1) hqq_gemm_f16(float* __restrict__ C) {
    extern __shared__ __align__(1024) char smem[];
    const uint32_t sb = smem_u32(smem);

    const int tid = threadIdx.x;
    const int wid = tid >> 5;
    const int lid = tid & 31;
    const int warp_m = wid >> 2;       // 0..1
    const int warp_n = wid & 3;        // 0..3

    // Supertile mapping: groups of 16 m-tiles across all 32 n-tiles.
    const int NT = OUT_F / BN;         // 32
    const int GM = 16;
    int bid = blockIdx.x;
    int group = bid / (GM * NT);
    int rem = bid - group * (GM * NT);
    int m_tile = group * GM + (rem % GM);
    int n_tile = rem / GM;

    const __half* Ab = g_xh + (size_t)m_tile * BM * IN_F;
    const __half* Bb = g_wh + (size_t)n_tile * BN * IN_F;

    // Loop-invariant loader offsets: 4 chunks/thread for A, same for B.
    uint32_t ld_s_off[4];
    size_t   ld_g_off[4];
    #pragma unroll
    for (int i = 0; i < 4; i++) {
        int c = tid + i * 256;                 // 0..1023
        int row = c >> 3, c16 = c & 7;
        ld_s_off[i] = SWZ((uint32_t)(row * 128 + c16 * 16));
        ld_g_off[i] = (size_t)row * IN_F + c16 * 8;
    }

    auto load_stage = [&](int stage, int kk) {
        uint32_t sA = sb + stage * STAGE_BYTES;
        uint32_t sB = sA + A_STAGE_BYTES;
        const __half* gA = Ab + kk;
        const __half* gB = Bb + kk;
        #pragma unroll
        for (int i = 0; i < 4; i++) CP_ASYNC16(sA + ld_s_off[i], gA + ld_g_off[i]);
        #pragma unroll
        for (int i = 0; i < 4; i++) CP_ASYNC16(sB + ld_s_off[i], gB + ld_g_off[i]);
    };

    // Prologue
    #pragma unroll
    for (int s = 0; s < STAGES - 1; s++) {
        load_stage(s, s * BK);
        CP_ASYNC_COMMIT();
    }

    // Accumulators: 4 m-subtiles x 4 n-subtiles x 4 floats
    float acc[4][4][4];
    #pragma unroll
    for (int i = 0; i < 4; i++)
        #pragma unroll
        for (int j = 0; j < 4; j++)
            #pragma unroll
            for (int q = 0; q < 4; q++) acc[i][j][q] = 0.0f;

    // Per-thread ldmatrix address components
    const int a_row = warp_m * 64 + (lid & 15);
    const int a_kc  = (lid >> 4) * 8;
    const int b_row = warp_n * 32 + ((lid >> 4) ? 8 : 0) + (lid & 7);
    const int b_kc  = ((lid >> 3) & 1) * 8;

    auto ld_a = [&](uint32_t (&af)[4][4], uint32_t sA, int kk) {
        #pragma unroll
        for (int mt = 0; mt < 4; mt++) {
            uint32_t off = (uint32_t)(a_row + mt * 16) * 128
                         + (uint32_t)(kk * 16 + a_kc) * 2;
            LDMATRIX_X4(af[mt][0], af[mt][1], af[mt][2], af[mt][3], sA + SWZ(off));
        }
    };
    auto ld_b = [&](uint32_t (&bf)[2][4], uint32_t sB, int kk) {
        #pragma unroll
        for (int p = 0; p < 2; p++) {
            uint32_t off = (uint32_t)(b_row + p * 16) * 128
                         + (uint32_t)(kk * 16 + b_kc) * 2;
            LDMATRIX_X4(bf[p][0], bf[p][1], bf[p][2], bf[p][3], sB + SWZ(off));
        }
    };

    // Double-buffered fragments
    uint32_t afr[2][4][4], bfr[2][2][4];

    for (int k = 0; k < K_ITERS; k++) {
        CP_ASYNC_WAIT(STAGES - 2);   // stage k landed
        __syncthreads();             // all warps past iter k-1 compute

        const int s = k % STAGES;
        const uint32_t sA = sb + s * STAGE_BYTES;
        const uint32_t sB = sA + A_STAGE_BYTES;

        // Refill target (stage consumed at iter k-1)
        const int kn = k + STAGES - 1;
        const bool do_load = (kn < K_ITERS);
        const uint32_t dA = sb + (kn % STAGES) * STAGE_BYTES;
        const uint32_t dB = dA + A_STAGE_BYTES;
        const __half* gA = Ab + (do_load ? kn * BK : 0);
        const __half* gB = Bb + (do_load ? kn * BK : 0);

        // Prime kk=0 fragments
        ld_a(afr[0], sA, 0);
        ld_b(bfr[0], sB, 0);

        #pragma unroll
        for (int kk = 0; kk < BK / 16; kk++) {       // 4 k-steps of 16
            const int cur = kk & 1, nxt = cur ^ 1;
            // Prefetch next fragments (hidden under this step's MMAs)
            if (kk < BK / 16 - 1) {
                ld_a(afr[nxt], sA, kk + 1);
                ld_b(bfr[nxt], sB, kk + 1);
            }
            // Drip 2 cp.async per kk step (8 total per iter)
            if (do_load) {
                CP_ASYNC16(dA + ld_s_off[kk], gA + ld_g_off[kk]);
                CP_ASYNC16(dB + ld_s_off[kk], gB + ld_g_off[kk]);
            }
            #pragma unroll
            for (int mt = 0; mt < 4; mt++)
                #pragma unroll
                for (int nt = 0; nt < 4; nt++)
                    MMA_16816(acc[mt][nt],
                              afr[cur][mt][0], afr[cur][mt][1],
                              afr[cur][mt][2], afr[cur][mt][3],
                              bfr[cur][nt >> 1][(nt & 1) * 2],
                              bfr[cur][nt >> 1][(nt & 1) * 2 + 1]);
        }
        CP_ASYNC_COMMIT();           // one group per iter (possibly empty)
    }

    // Epilogue: fragment layout -> global fp32, streaming stores
    const int m0 = m_tile * BM + warp_m * 64 + (lid >> 2);
    const int n0 = n_tile * BN + warp_n * 32 + (lid & 3) * 2;
    #pragma unroll
    for (int mt = 0; mt < 4; mt++) {
        #pragma unroll
        for (int nt = 0; nt < 4; nt++) {
            float* p0 = C + (size_t)(m0 + mt * 16) * OUT_F + (n0 + nt * 8);
            float* p1 = p0 + 8 * OUT_F;
            stcs_f2(p0, acc[mt][nt][0], acc[mt][nt][1]);
            stcs_f2(p1, acc[mt][nt][2], acc[mt][nt][3]);
        }
    }
}

// ---------------------------------------------------------------------------
// Launch
// ---------------------------------------------------------------------------
extern "C" void kernel_launch(void* const* d_in, const int* in_sizes, int n_in,
                              void* d_out, int out_size) {
    const float* x     = (const float*)d_in[0];
    const int*   Wq    = (const int*)d_in[1];
    const float* scale = (const float*)d_in[2];
    const float* zero  = (const float*)d_in[3];
    float* out = (float*)d_out;

    cudaFuncSetAttribute(hqq_gemm_f16, cudaFuncAttributeMaxDynamicSharedMemorySize, SMEM_TOTAL);

    conv_x_kernel<<<8388608 / 256, 256>>>(x);
    dequant_w_kernel<<<2097152 / 256, 256>>>(Wq, scale, zero);

    int grid = (M_TOTAL / BM) * (OUT_F / BN);   // 2048
    hqq_gemm_f16<<<grid, 256, SMEM_TOTAL>>>(out);
}

// round 7
// speedup vs baseline: 1.2239x; 1.0659x over previous
#include <cuda_runtime.h>
#include <cuda_fp16.h>
#include <cstdint>
#include <cstddef>

// ---------------------------------------------------------------------------
// Problem constants
// ---------------------------------------------------------------------------
#define OUT_F 4096
#define IN_F  4096
#define M_TOTAL 8192           // 4 * 2048

// GEMM tiling (fp16 mma.sync path — generic PTX, safe under target sm_100)
#define BM 128
#define BN 128
#define BK 64                  // halfs per stage k-slice = 128 bytes per row
#define STAGES 6
#define K_ITERS (IN_F / BK)    // 64 stages of k
#define PAIRS (K_ITERS / 2)    // 32 barrier iterations (2 stages per sync)
#define A_STAGE_BYTES (BM * BK * 2)            // 16384
#define B_STAGE_BYTES (BN * BK * 2)            // 16384
#define STAGE_BYTES (A_STAGE_BYTES + B_STAGE_BYTES)  // 32768
#define SMEM_TOTAL (STAGES * STAGE_BYTES)      // 196608

// ---------------------------------------------------------------------------
// Scratch (allocation-free rule: __device__ globals)
// ---------------------------------------------------------------------------
__device__ __align__(256) __half g_xh[(size_t)M_TOTAL * IN_F];  // x in fp16
__device__ __align__(256) __half g_wh[(size_t)OUT_F * IN_F];    // dequantized W in fp16

// ---------------------------------------------------------------------------
// Helpers
// ---------------------------------------------------------------------------
__device__ __forceinline__ uint32_t smem_u32(const void* p) {
    uint32_t a;
    asm("{ .reg .u64 t; cvta.to.shared.u64 t, %1; cvt.u32.u64 %0, t; }" : "=r"(a) : "l"(p));
    return a;
}

__device__ __forceinline__ uint32_t h2_bits(__half2 h) {
    return *reinterpret_cast<uint32_t*>(&h);
}

#define SWZ(off) ((off) ^ (((off) >> 3) & 0x70))

#define CP_ASYNC16(saddr, gptr) \
    asm volatile("cp.async.cg.shared.global [%0], [%1], 16;" :: "r"(saddr), "l"(gptr))
#define CP_ASYNC_COMMIT() asm volatile("cp.async.commit_group;" ::: "memory")
#define CP_ASYNC_WAIT(n)  asm volatile("cp.async.wait_group %0;" :: "n"(n) : "memory")

#define LDMATRIX_X4(r0, r1, r2, r3, addr)                                     \
    asm volatile("ldmatrix.sync.aligned.m8n8.x4.shared.b16 {%0,%1,%2,%3}, [%4];" \
                 : "=r"(r0), "=r"(r1), "=r"(r2), "=r"(r3) : "r"(addr))

#define MMA_16816(c, a0, a1, a2, a3, b0, b1)                                  \
    asm volatile("mma.sync.aligned.m16n8k16.row.col.f32.f16.f16.f32 "         \
                 "{%0,%1,%2,%3}, {%4,%5,%6,%7}, {%8,%9}, {%0,%1,%2,%3};"      \
                 : "+f"((c)[0]), "+f"((c)[1]), "+f"((c)[2]), "+f"((c)[3])     \
                 : "r"(a0), "r"(a1), "r"(a2), "r"(a3), "r"(b0), "r"(b1))

// Streaming store: C is write-once, never re-read -> don't pollute L2.
__device__ __forceinline__ void stcs_f2(float* p, float a, float b) {
    asm volatile("st.global.cs.v2.f32 [%0], {%1, %2};" :: "l"(p), "f"(a), "f"(b) : "memory");
}

// ---------------------------------------------------------------------------
// Prep kernel 1: x (fp32) -> fp16
// ---------------------------------------------------------------------------
__global__ void __launch_bounds__(256) conv_x_kernel(const float* __restrict__ x) {
    size_t j = (size_t)blockIdx.x * blockDim.x + threadIdx.x;   // [0, 8388608)
    float4 v = reinterpret_cast<const float4*>(x)[j];
    uint2 o;
    o.x = h2_bits(__floats2half2_rn(v.x, v.y));
    o.y = h2_bits(__floats2half2_rn(v.z, v.w));
    reinterpret_cast<uint2*>(g_xh)[j] = o;
}

// ---------------------------------------------------------------------------
// Prep kernel 2: HQQ int4 dequant -> fp16
// ---------------------------------------------------------------------------
__global__ void __launch_bounds__(256) dequant_w_kernel(
    const int* __restrict__ Wq, const float* __restrict__ scale,
    const float* __restrict__ zero) {
    size_t j = (size_t)blockIdx.x * blockDim.x + threadIdx.x;   // [0, 2097152)
    int4 v = reinterpret_cast<const int4*>(Wq)[j];
    size_t g = j >> 3;
    float s = scale[g];
    float z = zero[g];
    uint4 o;
    o.x = h2_bits(__floats2half2_rn(((float)(v.x & 15) - z) * s,
                                    ((float)(v.x >> 4) - z) * s));
    o.y = h2_bits(__floats2half2_rn(((float)(v.y & 15) - z) * s,
                                    ((float)(v.y >> 4) - z) * s));
    o.z = h2_bits(__floats2half2_rn(((float)(v.z & 15) - z) * s,
                                    ((float)(v.z >> 4) - z) * s));
    o.w = h2_bits(__floats2half2_rn(((float)(v.w & 15) - z) * s,
                                    ((float)(v.w >> 4) - z) * s));
    reinterpret_cast<uint4*>(g_wh)[j] = o;
}

// ---------------------------------------------------------------------------
// GEMM: C[M_TOTAL, OUT_F] = g_xh @ g_wh^T (fp16 in, fp32 accum)
// 256 threads = 8 warps as 2(m) x 4(n); warp tile 64x32.
// 6-stage cp.async pipeline, TWO stages per __syncthreads (32 barriers),
// fragment double-buffering across the whole 2-stage span.
// ---------------------------------------------------------------------------
__global__ void __launch_bounds__(256, 1) hqq_gemm_f16(float* __restrict__ C) {
    extern __shared__ __align__(1024) char smem[];
    const uint32_t sb = smem_u32(smem);

    const int tid = threadIdx.x;
    const int wid = tid >> 5;
    const int lid = tid & 31;
    const int warp_m = wid >> 2;       // 0..1
    const int warp_n = wid & 3;        // 0..3

    // Supertile mapping: groups of 16 m-tiles across all 32 n-tiles.
    const int NT = OUT_F / BN;         // 32
    const int GM = 16;
    int bid = blockIdx.x;
    int group = bid / (GM * NT);
    int rem = bid - group * (GM * NT);
    int m_tile = group * GM + (rem % GM);
    int n_tile = rem / GM;

    const __half* Ab = g_xh + (size_t)m_tile * BM * IN_F;
    const __half* Bb = g_wh + (size_t)n_tile * BN * IN_F;

    // Loop-invariant loader offsets: 4 chunks/thread for A, same for B.
    uint32_t ld_s_off[4];
    size_t   ld_g_off[4];
    #pragma unroll
    for (int i = 0; i < 4; i++) {
        int c = tid + i * 256;                 // 0..1023
        int row = c >> 3, c16 = c & 7;
        ld_s_off[i] = SWZ((uint32_t)(row * 128 + c16 * 16));
        ld_g_off[i] = (size_t)row * IN_F + c16 * 8;
    }

    auto load_stage = [&](int stage, int kk) {
        uint32_t sA = sb + stage * STAGE_BYTES;
        uint32_t sB = sA + A_STAGE_BYTES;
        const __half* gA = Ab + kk;
        const __half* gB = Bb + kk;
        #pragma unroll
        for (int i = 0; i < 4; i++) CP_ASYNC16(sA + ld_s_off[i], gA + ld_g_off[i]);
        #pragma unroll
        for (int i = 0; i < 4; i++) CP_ASYNC16(sB + ld_s_off[i], gB + ld_g_off[i]);
    };

    // Prologue: stages 0..3 (4 commits)
    #pragma unroll
    for (int s = 0; s < 4; s++) {
        load_stage(s, s * BK);
        CP_ASYNC_COMMIT();
    }

    // Accumulators: 4 m-subtiles x 4 n-subtiles x 4 floats
    float acc[4][4][4];
    #pragma unroll
    for (int i = 0; i < 4; i++)
        #pragma unroll
        for (int j = 0; j < 4; j++)
            #pragma unroll
            for (int q = 0; q < 4; q++) acc[i][j][q] = 0.0f;

    // Per-thread ldmatrix address components
    const int a_row = warp_m * 64 + (lid & 15);
    const int a_kc  = (lid >> 4) * 8;
    const int b_row = warp_n * 32 + ((lid >> 4) ? 8 : 0) + (lid & 7);
    const int b_kc  = ((lid >> 3) & 1) * 8;

    auto ld_a = [&](uint32_t (&af)[4][4], uint32_t sA, int kk) {
        #pragma unroll
        for (int mt = 0; mt < 4; mt++) {
            uint32_t off = (uint32_t)(a_row + mt * 16) * 128
                         + (uint32_t)(kk * 16 + a_kc) * 2;
            LDMATRIX_X4(af[mt][0], af[mt][1], af[mt][2], af[mt][3], sA + SWZ(off));
        }
    };
    auto ld_b = [&](uint32_t (&bf)[2][4], uint32_t sB, int kk) {
        #pragma unroll
        for (int p = 0; p < 2; p++) {
            uint32_t off = (uint32_t)(b_row + p * 16) * 128
                         + (uint32_t)(kk * 16 + b_kc) * 2;
            LDMATRIX_X4(bf[p][0], bf[p][1], bf[p][2], bf[p][3], sB + SWZ(off));
        }
    };

    // Double-buffered fragments
    uint32_t afr[2][4][4], bfr[2][2][4];

    for (int p = 0; p < PAIRS; p++) {
        CP_ASYNC_WAIT(2);            // stages 2p, 2p+1 landed (2 refill groups pending)
        __syncthreads();             // all warps past pair p-1 compute

        const uint32_t sA0 = sb + ((2 * p) % STAGES) * STAGE_BYTES;
        const uint32_t sB0 = sA0 + A_STAGE_BYTES;
        const uint32_t sA1 = sb + ((2 * p + 1) % STAGES) * STAGE_BYTES;
        const uint32_t sB1 = sA1 + A_STAGE_BYTES;

        // Refill targets: k-stages 2p+4 and 2p+5 (their smem slots were
        // consumed in pair p-1; barrier above makes reuse safe).
        const int kr0 = 2 * p + 4, kr1 = 2 * p + 5;
        const bool l0 = kr0 < K_ITERS, l1 = kr1 < K_ITERS;
        const uint32_t dA0 = sb + (kr0 % STAGES) * STAGE_BYTES;
        const uint32_t dB0 = dA0 + A_STAGE_BYTES;
        const uint32_t dA1 = sb + (kr1 % STAGES) * STAGE_BYTES;
        const uint32_t dB1 = dA1 + A_STAGE_BYTES;
        const __half* gA0 = Ab + (l0 ? kr0 * BK : 0);
        const __half* gB0 = Bb + (l0 ? kr0 * BK : 0);
        const __half* gA1 = Ab + (l1 ? kr1 * BK : 0);
        const __half* gB1 = Bb + (l1 ? kr1 * BK : 0);

        // Prime kk=0 fragments from stage 0 of the pair
        ld_a(afr[0], sA0, 0);
        ld_b(bfr[0], sB0, 0);

        #pragma unroll
        for (int kk = 0; kk < 8; kk++) {             // 8 k-steps of 16 across both stages
            const int cur = kk & 1, nxt = cur ^ 1;
            // Prefetch next fragments (stage s1's kk=0 prime hides under
            // s0's MMA tail — its data needs no extra barrier)
            if (kk < 7) {
                const uint32_t srcA = (kk + 1 < 4) ? sA0 : sA1;
                const uint32_t srcB = (kk + 1 < 4) ? sB0 : sB1;
                ld_a(afr[nxt], srcA, (kk + 1) & 3);
                ld_b(bfr[nxt], srcB, (kk + 1) & 3);
            }
            // Drip 2 cp.async per kk step; one commit group per refilled stage
            if (kk < 4) {
                if (l0) {
                    CP_ASYNC16(dA0 + ld_s_off[kk], gA0 + ld_g_off[kk]);
                    CP_ASYNC16(dB0 + ld_s_off[kk], gB0 + ld_g_off[kk]);
                }
            } else {
                if (l1) {
                    CP_ASYNC16(dA1 + ld_s_off[kk - 4], gA1 + ld_g_off[kk - 4]);
                    CP_ASYNC16(dB1 + ld_s_off[kk - 4], gB1 + ld_g_off[kk - 4]);
                }
            }
            if (kk == 3) CP_ASYNC_COMMIT();          // group for stage kr0
            #pragma unroll
            for (int mt = 0; mt < 4; mt++)
                #pragma unroll
                for (int nt = 0; nt < 4; nt++)
                    MMA_16816(acc[mt][nt],
                              afr[cur][mt][0], afr[cur][mt][1],
                              afr[cur][mt][2], afr[cur][mt][3],
                              bfr[cur][nt >> 1][(nt & 1) * 2],
                              bfr[cur][nt >> 1][(nt & 1) * 2 + 1]);
        }
        CP_ASYNC_COMMIT();                           // group for stage kr1
    }

    // Epilogue: fragment layout -> global fp32, streaming stores
    const int m0 = m_tile * BM + warp_m * 64 + (lid >> 2);
    const int n0 = n_tile * BN + warp_n * 32 + (lid & 3) * 2;
    #pragma unroll
    for (int mt = 0; mt < 4; mt++) {
        #pragma unroll
        for (int nt = 0; nt < 4; nt++) {
            float* p0 = C + (size_t)(m0 + mt * 16) * OUT_F + (n0 + nt * 8);
            float* p1 = p0 + 8 * OUT_F;
            stcs_f2(p0, acc[mt][nt][0], acc[mt][nt][1]);
            stcs_f2(p1, acc[mt][nt][2], acc[mt][nt][3]);
        }
    }
}

// ---------------------------------------------------------------------------
// Launch
// ---------------------------------------------------------------------------
extern "C" void kernel_launch(void* const* d_in, const int* in_sizes, int n_in,
                              void* d_out, int out_size) {
    const float* x     = (const float*)d_in[0];
    const int*   Wq    = (const int*)d_in[1];
    const float* scale = (const float*)d_in[2];
    const float* zero  = (const float*)d_in[3];
    float* out = (float*)d_out;

    cudaFuncSetAttribute(hqq_gemm_f16, cudaFuncAttributeMaxDynamicSharedMemorySize, SMEM_TOTAL);

    conv_x_kernel<<<8388608 / 256, 256>>>(x);
    dequant_w_kernel<<<2097152 / 256, 256>>>(Wq, scale, zero);

    int grid = (M_TOTAL / BM) * (OUT_F / BN);   // 2048
    hqq_gemm_f16<<<grid, 256, SMEM_TOTAL>>>(out);
}